// round 9
// baseline (speedup 1.0000x reference)
#include <cuda_runtime.h>
#include <cuda_fp16.h>
#include <cstdint>
#include <cstddef>

// Problem dims (fixed)
#define B_DIM 1024
#define M_DIM 4096
#define W_DIM 2
#define L_DIM 2
#define Z_DIM 64
#define H_DIM 8192   // M*W

// Output layout: x_recon [B*M], logcov [B*M], mu [B*Z], logvar [B*Z]
#define OFF_XREC  0
#define OFF_LCOV  (B_DIM * M_DIM)
#define OFF_MU    (2 * B_DIM * M_DIM)
#define OFF_LV    (2 * B_DIM * M_DIM + B_DIM * Z_DIM)

// -------- scratch (no allocations allowed; __device__ globals) --------
__device__ __half g_xh  [B_DIM * M_DIM];   // x in fp16
__device__ __half g_w1h [M_DIM * M_DIM];   // enc1_w in fp16
__device__ __half g_w2h [M_DIM * M_DIM];   // enc2_w in fp16
__device__ __half g_wch [128 * M_DIM];     // concat(mu_w, lv_w) in fp16
__device__ __half g_h1h [B_DIM * M_DIM];   // encoder layer-1 out (fp16)
__device__ __half g_h2h [B_DIM * M_DIM];   // encoder layer-2 out (fp16)
__device__ float  g_mulv[B_DIM * 128];
__device__ float  g_z[B_DIM * Z_DIM];

// -------- side stream + events (host-side resources, created once) --------
struct SideStream {
    cudaStream_t s = nullptr;
    cudaEvent_t fork = nullptr, join = nullptr;
    SideStream() {
        cudaStreamCreateWithFlags(&s, cudaStreamNonBlocking);
        cudaEventCreateWithFlags(&fork, cudaEventDisableTiming);
        cudaEventCreateWithFlags(&join, cudaEventDisableTiming);
    }
};
static SideStream g_side;

__device__ __forceinline__ float sigm(float x) { return 1.0f / (1.0f + expf(-x)); }

#define ACT_NONE 0
#define ACT_RELU 1

// ===================== fp32 -> fp16 conversion kernels =====================
#define NX8 (B_DIM * M_DIM / 8)
#define NW8 (M_DIM * M_DIM / 8)
#define NC8 (64 * M_DIM / 8)

__device__ __forceinline__ void cvt8(const float* __restrict__ in, __half* __restrict__ out, int j) {
    const float4* p = reinterpret_cast<const float4*>(in) + 2 * (size_t)j;
    float4 a = p[0], b = p[1];
    __half2 h0 = __floats2half2_rn(a.x, a.y);
    __half2 h1 = __floats2half2_rn(a.z, a.w);
    __half2 h2 = __floats2half2_rn(b.x, b.y);
    __half2 h3 = __floats2half2_rn(b.z, b.w);
    uint4 u;
    u.x = *reinterpret_cast<uint32_t*>(&h0);
    u.y = *reinterpret_cast<uint32_t*>(&h1);
    u.z = *reinterpret_cast<uint32_t*>(&h2);
    u.w = *reinterpret_cast<uint32_t*>(&h3);
    reinterpret_cast<uint4*>(out)[j] = u;
}

// A: x + enc1_w (needed before GEMM1)
__global__ void __launch_bounds__(256) f2hA_kernel(
    const float* __restrict__ x, const float* __restrict__ w1,
    __half* __restrict__ xh, __half* __restrict__ w1h)
{
    int i = blockIdx.x * 256 + threadIdx.x;
    if (i < NX8)                 cvt8(x,  xh,  i);
    else if (i < NX8 + NW8)      cvt8(w1, w1h, i - NX8);
}

// B: enc2_w + mu_w|lv_w (needed before GEMM2 / mulv) — runs on side stream
__global__ void __launch_bounds__(256) f2hB_kernel(
    const float* __restrict__ w2, const float* __restrict__ muw,
    const float* __restrict__ lvw,
    __half* __restrict__ w2h, __half* __restrict__ wch)
{
    int i = blockIdx.x * 256 + threadIdx.x;
    if (i < NW8)                 cvt8(w2,  w2h, i);
    else if (i < NW8 + NC8)      cvt8(muw, wch, i - NW8);
    else if (i < NW8 + 2 * NC8)  cvt8(lvw, wch + 64 * M_DIM, i - NW8 - NC8);
}

// ===================== fp16 cp.async tensor-core GEMM =====================
__device__ __forceinline__ uint32_t smem_u32(const void* p) {
    uint32_t a;
    asm("{ .reg .u64 t; cvta.to.shared.u64 t, %1; cvt.u32.u64 %0, t; }" : "=r"(a) : "l"(p));
    return a;
}
__device__ __forceinline__ void ldmx4(uint32_t* r, uint32_t addr) {
    asm volatile("ldmatrix.sync.aligned.m8n8.x4.shared.b16 {%0,%1,%2,%3}, [%4];"
                 : "=r"(r[0]), "=r"(r[1]), "=r"(r[2]), "=r"(r[3]) : "r"(addr));
}
__device__ __forceinline__ void mma_f16(float* d, const uint32_t* a, const uint32_t* b) {
    asm volatile(
        "mma.sync.aligned.m16n8k16.row.col.f32.f16.f16.f32 "
        "{%0,%1,%2,%3}, {%4,%5,%6,%7}, {%8,%9}, {%0,%1,%2,%3};\n"
        : "+f"(d[0]), "+f"(d[1]), "+f"(d[2]), "+f"(d[3])
        : "r"(a[0]), "r"(a[1]), "r"(a[2]), "r"(a[3]), "r"(b[0]), "r"(b[1]));
}
__device__ __forceinline__ void cp_async16(uint32_t smem_addr, const void* gptr) {
    asm volatile("cp.async.cg.shared.global [%0], [%1], 16;\n" :: "r"(smem_addr), "l"(gptr));
}
__device__ __forceinline__ void cp_commit() { asm volatile("cp.async.commit_group;\n"); }
template <int N> __device__ __forceinline__ void cp_wait() {
    asm volatile("cp.async.wait_group %0;\n" :: "n"(N));
}

#define HS_ROW   80
#define HS_TILE  (128 * HS_ROW)
#define HS_STAGE (2 * HS_TILE)
#define N_STAGES 4
#define SM_GEMM_TOTAL (N_STAGES * HS_STAGE)   // 81920 B dynamic

template <typename OT, int ACT, bool SPLITK>
__global__ void __launch_bounds__(512, 2) gemm_h16_kernel(
    const __half* __restrict__ A, const __half* __restrict__ Wt,
    const float* __restrict__ bias, OT* __restrict__ C,
    int Ndim, int Kstride, int Kchunk)
{
    extern __shared__ __align__(16) uint8_t dsm[];
    __shared__ float sbias[128];

    const int tid  = threadIdx.x;
    const int lane = tid & 31;
    const int warp = tid >> 5;
    const int wm   = (warp & 3) * 32;
    const int wn   = (warp >> 2) * 32;
    const int m0   = blockIdx.y * 128;
    const int n0   = blockIdx.x * 128;
    const int koff = SPLITK ? blockIdx.z * Kchunk : 0;
    const uint32_t sb = smem_u32(dsm);

    if (!SPLITK && tid < 128) sbias[tid] = bias[n0 + tid];

    const int rC = tid >> 2;
    const int kC = (tid & 3) * 8;
    const uint32_t dC = (uint32_t)rC * HS_ROW + kC * 2;

    const __half* Ab = A  + (size_t)m0 * Kstride + koff;
    const __half* Bb = Wt + (size_t)n0 * Kstride + koff;

    const int T = Kchunk >> 5;

    auto issue = [&](int it) {
        uint32_t st = sb + (it & (N_STAGES - 1)) * HS_STAGE;
        cp_async16(st + dC,           Ab + (size_t)rC * Kstride + it * 32 + kC);
        cp_async16(st + HS_TILE + dC, Bb + (size_t)rC * Kstride + it * 32 + kC);
        cp_commit();
    };

    const uint32_t a_lm = ((lane & 7) + ((lane >> 3) & 1) * 8) * HS_ROW + ((lane >> 4) & 1) * 16;
    const uint32_t b_lm = ((lane & 7) + ((lane >> 4) & 1) * 8) * HS_ROW + ((lane >> 3) & 1) * 16;

    float acc[2][4][4];
#pragma unroll
    for (int i = 0; i < 2; i++)
#pragma unroll
        for (int j = 0; j < 4; j++)
#pragma unroll
            for (int r = 0; r < 4; r++) acc[i][j][r] = 0.0f;

#pragma unroll
    for (int i = 0; i < N_STAGES - 1; i++) issue(i);

    for (int it = 0; it < T; ++it) {
        cp_wait<N_STAGES - 2>();
        __syncthreads();

        if (it + N_STAGES - 1 < T) issue(it + N_STAGES - 1);
        else cp_commit();

        const uint32_t sa  = sb + (it & (N_STAGES - 1)) * HS_STAGE;
        const uint32_t sbm = sa + HS_TILE;
#pragma unroll
        for (int kk = 0; kk < 2; kk++) {
            uint32_t af[2][4], bf[2][4];
#pragma unroll
            for (int im = 0; im < 2; im++)
                ldmx4(af[im], sa + (wm + im * 16) * HS_ROW + a_lm + kk * 32);
#pragma unroll
            for (int jn = 0; jn < 2; jn++)
                ldmx4(bf[jn], sbm + (wn + jn * 16) * HS_ROW + b_lm + kk * 32);
#pragma unroll
            for (int im = 0; im < 2; im++)
#pragma unroll
                for (int jn = 0; jn < 2; jn++) {
                    mma_f16(acc[im][2 * jn],     af[im], &bf[jn][0]);
                    mma_f16(acc[im][2 * jn + 1], af[im], &bf[jn][2]);
                }
        }
    }

    const int g = lane >> 2, t = lane & 3;
#pragma unroll
    for (int im = 0; im < 2; im++) {
        int r0 = m0 + wm + im * 16 + g;
#pragma unroll
        for (int in_ = 0; in_ < 4; in_++) {
            int cl = wn + in_ * 8 + t * 2;
            int c = n0 + cl;
            if (SPLITK) {
                float* Cf = reinterpret_cast<float*>(C);
                atomicAdd(&Cf[(size_t)r0 * Ndim + c],           acc[im][in_][0]);
                atomicAdd(&Cf[(size_t)r0 * Ndim + c + 1],       acc[im][in_][1]);
                atomicAdd(&Cf[(size_t)(r0 + 8) * Ndim + c],     acc[im][in_][2]);
                atomicAdd(&Cf[(size_t)(r0 + 8) * Ndim + c + 1], acc[im][in_][3]);
            } else {
                float b0v = sbias[cl], b1v = sbias[cl + 1];
                float v00 = acc[im][in_][0] + b0v;
                float v01 = acc[im][in_][1] + b1v;
                float v10 = acc[im][in_][2] + b0v;
                float v11 = acc[im][in_][3] + b1v;
                if (ACT == ACT_RELU) {
                    v00 = fmaxf(v00, 0.0f); v01 = fmaxf(v01, 0.0f);
                    v10 = fmaxf(v10, 0.0f); v11 = fmaxf(v11, 0.0f);
                }
                if (sizeof(OT) == 2) {
                    __half* Ch = reinterpret_cast<__half*>(C);
                    __half2 lo = __floats2half2_rn(v00, v01);
                    __half2 hi = __floats2half2_rn(v10, v11);
                    *reinterpret_cast<__half2*>(&Ch[(size_t)r0 * Ndim + c]) = lo;
                    *reinterpret_cast<__half2*>(&Ch[(size_t)(r0 + 8) * Ndim + c]) = hi;
                } else {
                    float* Cf = reinterpret_cast<float*>(C);
                    *reinterpret_cast<float2*>(&Cf[(size_t)r0 * Ndim + c]) = make_float2(v00, v01);
                    *reinterpret_cast<float2*>(&Cf[(size_t)(r0 + 8) * Ndim + c]) = make_float2(v10, v11);
                }
            }
        }
    }
}

// ===================== reparameterization + mu/logvar output =====================
__global__ void z_kernel(const float* __restrict__ mulv, const float* __restrict__ eps,
                         const float* __restrict__ mu_b, const float* __restrict__ lv_b,
                         float* __restrict__ z, float* __restrict__ out)
{
    int idx = blockIdx.x * 256 + threadIdx.x;
    if (idx >= B_DIM * Z_DIM) return;
    int b = idx >> 6, j = idx & 63;
    float mu = mulv[(size_t)b * 128 + j]      + mu_b[j];
    float lv = mulv[(size_t)b * 128 + 64 + j] + lv_b[j];
    z[idx] = mu + expf(0.5f * lv) * eps[idx];
    out[OFF_MU + idx] = mu;
    out[OFF_LV + idx] = lv;
}

// ===================== fused decoder: fulcon GEMM + block-diag layers + output =======
#define DEC_SMEM (2 * 64 * 132 * 4)    // 67584 B

__global__ void __launch_bounds__(256) decoder_kernel(
    const float* __restrict__ z,
    const float* __restrict__ m_ful_w, const float* __restrict__ m_ful_b,
    const float* __restrict__ m_h_w,   const float* __restrict__ m_h_b,
    const float* __restrict__ m_out_w, const float* __restrict__ m_out_b,
    const float* __restrict__ c_ful_w, const float* __restrict__ c_ful_b,
    const float* __restrict__ c_h_w,   const float* __restrict__ c_h_b,
    const float* __restrict__ c_out_w, const float* __restrict__ c_out_b,
    float* __restrict__ out)
{
    extern __shared__ float ds[];
    float* Zs = ds;               // [64 k][132]
    float* Ws = ds + 64 * 132;    // [64 k][132]
    __shared__ float sfb[128];

    const bool mean = (blockIdx.z == 0);
    const float* fw = mean ? m_ful_w : c_ful_w;
    const float* fb = mean ? m_ful_b : c_ful_b;
    const float* hw = mean ? m_h_w   : c_h_w;
    const float* hb = mean ? m_h_b   : c_h_b;
    const float* ow = mean ? m_out_w : c_out_w;
    const float* ob = mean ? m_out_b : c_out_b;
    const int out_off = mean ? OFF_XREC : OFF_LCOV;

    const int tid = threadIdx.x;
    const int tx  = tid & 15;
    const int ty  = tid >> 4;
    const int n0  = blockIdx.x * 128;
    const int b0  = blockIdx.y * 128;

#pragma unroll
    for (int it = 0; it < 8; it++) {
        int idx = tid + it * 256;
        int row = idx >> 4, kq = (idx & 15) * 4;
        float4 v = *reinterpret_cast<const float4*>(&z[(size_t)(b0 + row) * 64 + kq]);
        Zs[(kq + 0) * 132 + row] = v.x; Zs[(kq + 1) * 132 + row] = v.y;
        Zs[(kq + 2) * 132 + row] = v.z; Zs[(kq + 3) * 132 + row] = v.w;
    }
#pragma unroll
    for (int it = 0; it < 8; it++) {
        int idx = tid + it * 256;
        int row = idx >> 4, kq = (idx & 15) * 4;
        float4 v = *reinterpret_cast<const float4*>(&fw[(size_t)(n0 + row) * 64 + kq]);
        Ws[(kq + 0) * 132 + row] = v.x; Ws[(kq + 1) * 132 + row] = v.y;
        Ws[(kq + 2) * 132 + row] = v.z; Ws[(kq + 3) * 132 + row] = v.w;
    }
    if (tid < 128) sfb[tid] = fb[n0 + tid];
    __syncthreads();

    float acc[8][8];
#pragma unroll
    for (int i = 0; i < 8; i++)
#pragma unroll
        for (int j = 0; j < 8; j++) acc[i][j] = 0.0f;

#pragma unroll 4
    for (int k = 0; k < 64; k++) {
        float ar[8], br[8];
        *reinterpret_cast<float4*>(&ar[0]) = *reinterpret_cast<const float4*>(&Zs[k * 132 + ty * 8]);
        *reinterpret_cast<float4*>(&ar[4]) = *reinterpret_cast<const float4*>(&Zs[k * 132 + ty * 8 + 4]);
        *reinterpret_cast<float4*>(&br[0]) = *reinterpret_cast<const float4*>(&Ws[k * 132 + tx * 8]);
        *reinterpret_cast<float4*>(&br[4]) = *reinterpret_cast<const float4*>(&Ws[k * 132 + tx * 8 + 4]);
#pragma unroll
        for (int i = 0; i < 8; i++)
#pragma unroll
            for (int j = 0; j < 8; j++)
                acc[i][j] = fmaf(ar[i], br[j], acc[i][j]);
    }
#pragma unroll
    for (int i = 0; i < 8; i++)
#pragma unroll
        for (int j = 0; j < 8; j++)
            acc[i][j] = sigm(acc[i][j] + sfb[tx * 8 + j]);

    __syncthreads();
    float* Os = ds;    // [128 b][64 m]

#pragma unroll
    for (int jj = 0; jj < 4; jj++) {
        int m = (n0 >> 1) + tx * 4 + jj;
        float4 w0 = *reinterpret_cast<const float4*>(&hw[(size_t)m * 4]);
        float4 w1 = *reinterpret_cast<const float4*>(&hw[((size_t)M_DIM + m) * 4]);
        float b00 = hb[2 * m],          b01 = hb[2 * m + 1];
        float b10 = hb[H_DIM + 2 * m],  b11 = hb[H_DIM + 2 * m + 1];
        float2 owv = *reinterpret_cast<const float2*>(&ow[2 * m]);
        float obv = ob[m];
#pragma unroll
        for (int i = 0; i < 8; i++) {
            float a0 = acc[i][2 * jj], a1 = acc[i][2 * jj + 1];
            float t0 = sigm(fmaf(a0, w0.x, fmaf(a1, w0.y, b00)));
            float t1 = sigm(fmaf(a0, w0.z, fmaf(a1, w0.w, b01)));
            a0 = sigm(fmaf(t0, w1.x, fmaf(t1, w1.y, b10)));
            a1 = sigm(fmaf(t0, w1.z, fmaf(t1, w1.w, b11)));
            Os[(ty * 8 + i) * 64 + tx * 4 + jj] = fmaf(a0, owv.x, fmaf(a1, owv.y, obv));
        }
    }
    __syncthreads();

#pragma unroll
    for (int it = 0; it < 8; it++) {
        int idx = tid + it * 256;
        int row = idx >> 4, mq = (idx & 15) * 4;
        float4 v = *reinterpret_cast<const float4*>(&Os[row * 64 + mq]);
        *reinterpret_cast<float4*>(&out[out_off + (size_t)(b0 + row) * M_DIM + (n0 >> 1) + mq]) = v;
    }
}

// ===================== launch =====================
extern "C" void kernel_launch(void* const* d_in, const int* in_sizes, int n_in,
                              void* d_out, int out_size)
{
    const float* x        = (const float*)d_in[0];
    const float* eps      = (const float*)d_in[1];
    const float* enc1_w   = (const float*)d_in[2];
    const float* enc1_b   = (const float*)d_in[3];
    const float* enc2_w   = (const float*)d_in[4];
    const float* enc2_b   = (const float*)d_in[5];
    const float* mu_w     = (const float*)d_in[6];
    const float* mu_b     = (const float*)d_in[7];
    const float* lv_w     = (const float*)d_in[8];
    const float* lv_b     = (const float*)d_in[9];
    const float* m_ful_w  = (const float*)d_in[10];
    const float* m_ful_b  = (const float*)d_in[11];
    const float* m_h_w    = (const float*)d_in[12];
    const float* m_h_b    = (const float*)d_in[13];
    const float* m_out_w  = (const float*)d_in[14];
    const float* m_out_b  = (const float*)d_in[15];
    const float* c_ful_w  = (const float*)d_in[16];
    const float* c_ful_b  = (const float*)d_in[17];
    const float* c_h_w    = (const float*)d_in[18];
    const float* c_h_b    = (const float*)d_in[19];
    const float* c_out_w  = (const float*)d_in[20];
    const float* c_out_b  = (const float*)d_in[21];
    float* out = (float*)d_out;

    __half *xh, *w1h, *w2h, *wch, *h1h, *h2h;
    float *mulv, *z;
    cudaGetSymbolAddress((void**)&xh,   g_xh);
    cudaGetSymbolAddress((void**)&w1h,  g_w1h);
    cudaGetSymbolAddress((void**)&w2h,  g_w2h);
    cudaGetSymbolAddress((void**)&wch,  g_wch);
    cudaGetSymbolAddress((void**)&h1h,  g_h1h);
    cudaGetSymbolAddress((void**)&h2h,  g_h2h);
    cudaGetSymbolAddress((void**)&mulv, g_mulv);
    cudaGetSymbolAddress((void**)&z,    g_z);

    cudaFuncSetAttribute((const void*)gemm_h16_kernel<__half, ACT_RELU, false>,
                         cudaFuncAttributeMaxDynamicSharedMemorySize, SM_GEMM_TOTAL);
    cudaFuncSetAttribute((const void*)gemm_h16_kernel<float, ACT_NONE, true>,
                         cudaFuncAttributeMaxDynamicSharedMemorySize, SM_GEMM_TOTAL);
    cudaFuncSetAttribute((const void*)decoder_kernel,
                         cudaFuncAttributeMaxDynamicSharedMemorySize, DEC_SMEM);

    // ---- fork side stream: convert w2 + mu|lv weights and zero mulv, overlapped
    //      with f2hA + GEMM1 on the main stream ----
    cudaEventRecord(g_side.fork, 0);
    cudaStreamWaitEvent(g_side.s, g_side.fork, 0);
    f2hB_kernel<<<(NW8 + 2 * NC8 + 255) / 256, 256, 0, g_side.s>>>(
        enc2_w, mu_w, lv_w, w2h, wch);
    cudaMemsetAsync(mulv, 0, B_DIM * 128 * sizeof(float), g_side.s);
    cudaEventRecord(g_side.join, g_side.s);

    // ---- main stream: x + enc1_w conversion, then GEMM1 ----
    f2hA_kernel<<<(NX8 + NW8 + 255) / 256, 256>>>(x, enc1_w, xh, w1h);

    dim3 g1(M_DIM / 128, B_DIM / 128);
    gemm_h16_kernel<__half, ACT_RELU, false><<<g1, 512, SM_GEMM_TOTAL>>>(
        xh,  w1h, enc1_b, h1h, M_DIM, M_DIM, M_DIM);

    // ---- join: need w2h (+ wch, mulv zeroed) before GEMM2 / mulv ----
    cudaStreamWaitEvent(0, g_side.join, 0);

    gemm_h16_kernel<__half, ACT_RELU, false><<<g1, 512, SM_GEMM_TOTAL>>>(
        h1h, w2h, enc2_b, h2h, M_DIM, M_DIM, M_DIM);

    // ---- mu / logvar projection: split-K tensor GEMM (atomic accumulate) ----
    dim3 g2(1, B_DIM / 128, 8);   // N=128 tile, 8 M-tiles, 8 K-chunks of 512
    gemm_h16_kernel<float, ACT_NONE, true><<<g2, 512, SM_GEMM_TOTAL>>>(
        h2h, wch, nullptr, mulv, 128, M_DIM, 512);

    z_kernel<<<(B_DIM * Z_DIM + 255) / 256, 256>>>(mulv, eps, mu_b, lv_b, z, out);

    // ---- fused decoder (both branches) ----
    dim3 g3(H_DIM / 128, B_DIM / 128, 2);
    decoder_kernel<<<g3, 256, DEC_SMEM>>>(
        z,
        m_ful_w, m_ful_b, m_h_w, m_h_b, m_out_w, m_out_b,
        c_ful_w, c_ful_b, c_h_w, c_h_b, c_out_w, c_out_b,
        out);
}

// round 10
// speedup vs baseline: 1.0054x; 1.0054x over previous
#include <cuda_runtime.h>
#include <cuda_fp16.h>
#include <cstdint>
#include <cstddef>

// Problem dims (fixed)
#define B_DIM 1024
#define M_DIM 4096
#define W_DIM 2
#define L_DIM 2
#define Z_DIM 64
#define H_DIM 8192   // M*W

// Output layout: x_recon [B*M], logcov [B*M], mu [B*Z], logvar [B*Z]
#define OFF_XREC  0
#define OFF_LCOV  (B_DIM * M_DIM)
#define OFF_MU    (2 * B_DIM * M_DIM)
#define OFF_LV    (2 * B_DIM * M_DIM + B_DIM * Z_DIM)

// -------- scratch (no allocations allowed; __device__ globals) --------
__device__ __half g_xh  [B_DIM * M_DIM];   // x in fp16
__device__ __half g_w1h [M_DIM * M_DIM];   // enc1_w in fp16
__device__ __half g_w2h [M_DIM * M_DIM];   // enc2_w in fp16
__device__ __half g_wch [128 * M_DIM];     // concat(mu_w, lv_w) in fp16
__device__ __half g_h1h [B_DIM * M_DIM];   // encoder layer-1 out (fp16)
__device__ __half g_h2h [B_DIM * M_DIM];   // encoder layer-2 out (fp16)
__device__ float  g_mulv[B_DIM * 128];
__device__ float  g_z[B_DIM * Z_DIM];

// -------- side stream + events (host-side resources, created once) --------
struct SideStream {
    cudaStream_t s = nullptr;
    cudaEvent_t fork = nullptr, join = nullptr;
    SideStream() {
        cudaStreamCreateWithFlags(&s, cudaStreamNonBlocking);
        cudaEventCreateWithFlags(&fork, cudaEventDisableTiming);
        cudaEventCreateWithFlags(&join, cudaEventDisableTiming);
    }
};
static SideStream g_side;

__device__ __forceinline__ float sigm(float x) { return 1.0f / (1.0f + expf(-x)); }

#define ACT_NONE 0
#define ACT_RELU 1

// ===================== fp32 -> fp16 conversion kernels =====================
#define NX8 (B_DIM * M_DIM / 8)
#define NW8 (M_DIM * M_DIM / 8)
#define NC8 (64 * M_DIM / 8)

__device__ __forceinline__ void cvt8(const float* __restrict__ in, __half* __restrict__ out, int j) {
    const float4* p = reinterpret_cast<const float4*>(in) + 2 * (size_t)j;
    float4 a = p[0], b = p[1];
    __half2 h0 = __floats2half2_rn(a.x, a.y);
    __half2 h1 = __floats2half2_rn(a.z, a.w);
    __half2 h2 = __floats2half2_rn(b.x, b.y);
    __half2 h3 = __floats2half2_rn(b.z, b.w);
    uint4 u;
    u.x = *reinterpret_cast<uint32_t*>(&h0);
    u.y = *reinterpret_cast<uint32_t*>(&h1);
    u.z = *reinterpret_cast<uint32_t*>(&h2);
    u.w = *reinterpret_cast<uint32_t*>(&h3);
    reinterpret_cast<uint4*>(out)[j] = u;
}

// A: x + enc1_w (needed before GEMM1)
__global__ void __launch_bounds__(256) f2hA_kernel(
    const float* __restrict__ x, const float* __restrict__ w1,
    __half* __restrict__ xh, __half* __restrict__ w1h)
{
    int i = blockIdx.x * 256 + threadIdx.x;
    if (i < NX8)                 cvt8(x,  xh,  i);
    else if (i < NX8 + NW8)      cvt8(w1, w1h, i - NX8);
}

// B: enc2_w + mu_w|lv_w — runs on side stream, overlapped with GEMM1
__global__ void __launch_bounds__(256) f2hB_kernel(
    const float* __restrict__ w2, const float* __restrict__ muw,
    const float* __restrict__ lvw,
    __half* __restrict__ w2h, __half* __restrict__ wch)
{
    int i = blockIdx.x * 256 + threadIdx.x;
    if (i < NW8)                 cvt8(w2,  w2h, i);
    else if (i < NW8 + NC8)      cvt8(muw, wch, i - NW8);
    else if (i < NW8 + 2 * NC8)  cvt8(lvw, wch + 64 * M_DIM, i - NW8 - NC8);
}

// ===================== fp16 cp.async tensor-core GEMM =====================
__device__ __forceinline__ uint32_t smem_u32(const void* p) {
    uint32_t a;
    asm("{ .reg .u64 t; cvta.to.shared.u64 t, %1; cvt.u32.u64 %0, t; }" : "=r"(a) : "l"(p));
    return a;
}
__device__ __forceinline__ void ldmx4(uint32_t* r, uint32_t addr) {
    asm volatile("ldmatrix.sync.aligned.m8n8.x4.shared.b16 {%0,%1,%2,%3}, [%4];"
                 : "=r"(r[0]), "=r"(r[1]), "=r"(r[2]), "=r"(r[3]) : "r"(addr));
}
__device__ __forceinline__ void mma_f16(float* d, const uint32_t* a, const uint32_t* b) {
    asm volatile(
        "mma.sync.aligned.m16n8k16.row.col.f32.f16.f16.f32 "
        "{%0,%1,%2,%3}, {%4,%5,%6,%7}, {%8,%9}, {%0,%1,%2,%3};\n"
        : "+f"(d[0]), "+f"(d[1]), "+f"(d[2]), "+f"(d[3])
        : "r"(a[0]), "r"(a[1]), "r"(a[2]), "r"(a[3]), "r"(b[0]), "r"(b[1]));
}
__device__ __forceinline__ void cp_async16(uint32_t smem_addr, const void* gptr) {
    asm volatile("cp.async.cg.shared.global [%0], [%1], 16;\n" :: "r"(smem_addr), "l"(gptr));
}
__device__ __forceinline__ void cp_commit() { asm volatile("cp.async.commit_group;\n"); }
template <int N> __device__ __forceinline__ void cp_wait() {
    asm volatile("cp.async.wait_group %0;\n" :: "n"(N));
}

#define HS_ROW   80
#define HS_TILE  (128 * HS_ROW)
#define HS_STAGE (2 * HS_TILE)
#define N_STAGES 4
#define SM_GEMM_TOTAL (N_STAGES * HS_STAGE)   // 81920 B dynamic

template <typename OT, int ACT, bool SPLITK>
__global__ void __launch_bounds__(512, 2) gemm_h16_kernel(
    const __half* __restrict__ A, const __half* __restrict__ Wt,
    const float* __restrict__ bias, OT* __restrict__ C,
    int Ndim, int Kstride, int Kchunk)
{
    extern __shared__ __align__(16) uint8_t dsm[];
    __shared__ float sbias[128];

    const int tid  = threadIdx.x;
    const int lane = tid & 31;
    const int warp = tid >> 5;
    const int wm   = (warp & 3) * 32;
    const int wn   = (warp >> 2) * 32;
    const int m0   = blockIdx.y * 128;
    const int n0   = blockIdx.x * 128;
    const int koff = SPLITK ? blockIdx.z * Kchunk : 0;
    const uint32_t sb = smem_u32(dsm);

    if (!SPLITK && tid < 128) sbias[tid] = bias[n0 + tid];

    const int rC = tid >> 2;
    const int kC = (tid & 3) * 8;
    const uint32_t dC = (uint32_t)rC * HS_ROW + kC * 2;

    const __half* Ab = A  + (size_t)m0 * Kstride + koff;
    const __half* Bb = Wt + (size_t)n0 * Kstride + koff;

    const int T = Kchunk >> 5;

    auto issue = [&](int it) {
        uint32_t st = sb + (it & (N_STAGES - 1)) * HS_STAGE;
        cp_async16(st + dC,           Ab + (size_t)rC * Kstride + it * 32 + kC);
        cp_async16(st + HS_TILE + dC, Bb + (size_t)rC * Kstride + it * 32 + kC);
        cp_commit();
    };

    const uint32_t a_lm = ((lane & 7) + ((lane >> 3) & 1) * 8) * HS_ROW + ((lane >> 4) & 1) * 16;
    const uint32_t b_lm = ((lane & 7) + ((lane >> 4) & 1) * 8) * HS_ROW + ((lane >> 3) & 1) * 16;

    float acc[2][4][4];
#pragma unroll
    for (int i = 0; i < 2; i++)
#pragma unroll
        for (int j = 0; j < 4; j++)
#pragma unroll
            for (int r = 0; r < 4; r++) acc[i][j][r] = 0.0f;

#pragma unroll
    for (int i = 0; i < N_STAGES - 1; i++) issue(i);

    for (int it = 0; it < T; ++it) {
        cp_wait<N_STAGES - 2>();
        __syncthreads();

        if (it + N_STAGES - 1 < T) issue(it + N_STAGES - 1);
        else cp_commit();

        const uint32_t sa  = sb + (it & (N_STAGES - 1)) * HS_STAGE;
        const uint32_t sbm = sa + HS_TILE;
#pragma unroll
        for (int kk = 0; kk < 2; kk++) {
            uint32_t af[2][4], bf[2][4];
#pragma unroll
            for (int im = 0; im < 2; im++)
                ldmx4(af[im], sa + (wm + im * 16) * HS_ROW + a_lm + kk * 32);
#pragma unroll
            for (int jn = 0; jn < 2; jn++)
                ldmx4(bf[jn], sbm + (wn + jn * 16) * HS_ROW + b_lm + kk * 32);
#pragma unroll
            for (int im = 0; im < 2; im++)
#pragma unroll
                for (int jn = 0; jn < 2; jn++) {
                    mma_f16(acc[im][2 * jn],     af[im], &bf[jn][0]);
                    mma_f16(acc[im][2 * jn + 1], af[im], &bf[jn][2]);
                }
        }
    }

    const int g = lane >> 2, t = lane & 3;
#pragma unroll
    for (int im = 0; im < 2; im++) {
        int r0 = m0 + wm + im * 16 + g;
#pragma unroll
        for (int in_ = 0; in_ < 4; in_++) {
            int cl = wn + in_ * 8 + t * 2;
            int c = n0 + cl;
            if (SPLITK) {
                float* Cf = reinterpret_cast<float*>(C);
                atomicAdd(&Cf[(size_t)r0 * Ndim + c],           acc[im][in_][0]);
                atomicAdd(&Cf[(size_t)r0 * Ndim + c + 1],       acc[im][in_][1]);
                atomicAdd(&Cf[(size_t)(r0 + 8) * Ndim + c],     acc[im][in_][2]);
                atomicAdd(&Cf[(size_t)(r0 + 8) * Ndim + c + 1], acc[im][in_][3]);
            } else {
                float b0v = sbias[cl], b1v = sbias[cl + 1];
                float v00 = acc[im][in_][0] + b0v;
                float v01 = acc[im][in_][1] + b1v;
                float v10 = acc[im][in_][2] + b0v;
                float v11 = acc[im][in_][3] + b1v;
                if (ACT == ACT_RELU) {
                    v00 = fmaxf(v00, 0.0f); v01 = fmaxf(v01, 0.0f);
                    v10 = fmaxf(v10, 0.0f); v11 = fmaxf(v11, 0.0f);
                }
                if (sizeof(OT) == 2) {
                    __half* Ch = reinterpret_cast<__half*>(C);
                    __half2 lo = __floats2half2_rn(v00, v01);
                    __half2 hi = __floats2half2_rn(v10, v11);
                    *reinterpret_cast<__half2*>(&Ch[(size_t)r0 * Ndim + c]) = lo;
                    *reinterpret_cast<__half2*>(&Ch[(size_t)(r0 + 8) * Ndim + c]) = hi;
                } else {
                    float* Cf = reinterpret_cast<float*>(C);
                    *reinterpret_cast<float2*>(&Cf[(size_t)r0 * Ndim + c]) = make_float2(v00, v01);
                    *reinterpret_cast<float2*>(&Cf[(size_t)(r0 + 8) * Ndim + c]) = make_float2(v10, v11);
                }
            }
        }
    }
}

// ===================== reparameterization + mu/logvar output =====================
__global__ void z_kernel(const float* __restrict__ mulv, const float* __restrict__ eps,
                         const float* __restrict__ mu_b, const float* __restrict__ lv_b,
                         float* __restrict__ z, float* __restrict__ out)
{
    int idx = blockIdx.x * 256 + threadIdx.x;
    if (idx >= B_DIM * Z_DIM) return;
    int b = idx >> 6, j = idx & 63;
    float mu = mulv[(size_t)b * 128 + j]      + mu_b[j];
    float lv = mulv[(size_t)b * 128 + 64 + j] + lv_b[j];
    z[idx] = mu + expf(0.5f * lv) * eps[idx];
    out[OFF_MU + idx] = mu;
    out[OFF_LV + idx] = lv;
}

// ===================== fused decoder: fulcon GEMM + block-diag layers + output =======
#define DEC_SMEM (2 * 64 * 132 * 4)    // 67584 B

__global__ void __launch_bounds__(256) decoder_kernel(
    const float* __restrict__ z,
    const float* __restrict__ m_ful_w, const float* __restrict__ m_ful_b,
    const float* __restrict__ m_h_w,   const float* __restrict__ m_h_b,
    const float* __restrict__ m_out_w, const float* __restrict__ m_out_b,
    const float* __restrict__ c_ful_w, const float* __restrict__ c_ful_b,
    const float* __restrict__ c_h_w,   const float* __restrict__ c_h_b,
    const float* __restrict__ c_out_w, const float* __restrict__ c_out_b,
    float* __restrict__ out)
{
    extern __shared__ float ds[];
    float* Zs = ds;               // [64 k][132]
    float* Ws = ds + 64 * 132;    // [64 k][132]
    __shared__ float sfb[128];

    const bool mean = (blockIdx.z == 0);
    const float* fw = mean ? m_ful_w : c_ful_w;
    const float* fb = mean ? m_ful_b : c_ful_b;
    const float* hw = mean ? m_h_w   : c_h_w;
    const float* hb = mean ? m_h_b   : c_h_b;
    const float* ow = mean ? m_out_w : c_out_w;
    const float* ob = mean ? m_out_b : c_out_b;
    const int out_off = mean ? OFF_XREC : OFF_LCOV;

    const int tid = threadIdx.x;
    const int tx  = tid & 15;
    const int ty  = tid >> 4;
    const int n0  = blockIdx.x * 128;
    const int b0  = blockIdx.y * 128;

#pragma unroll
    for (int it = 0; it < 8; it++) {
        int idx = tid + it * 256;
        int row = idx >> 4, kq = (idx & 15) * 4;
        float4 v = *reinterpret_cast<const float4*>(&z[(size_t)(b0 + row) * 64 + kq]);
        Zs[(kq + 0) * 132 + row] = v.x; Zs[(kq + 1) * 132 + row] = v.y;
        Zs[(kq + 2) * 132 + row] = v.z; Zs[(kq + 3) * 132 + row] = v.w;
    }
#pragma unroll
    for (int it = 0; it < 8; it++) {
        int idx = tid + it * 256;
        int row = idx >> 4, kq = (idx & 15) * 4;
        float4 v = *reinterpret_cast<const float4*>(&fw[(size_t)(n0 + row) * 64 + kq]);
        Ws[(kq + 0) * 132 + row] = v.x; Ws[(kq + 1) * 132 + row] = v.y;
        Ws[(kq + 2) * 132 + row] = v.z; Ws[(kq + 3) * 132 + row] = v.w;
    }
    if (tid < 128) sfb[tid] = fb[n0 + tid];
    __syncthreads();

    float acc[8][8];
#pragma unroll
    for (int i = 0; i < 8; i++)
#pragma unroll
        for (int j = 0; j < 8; j++) acc[i][j] = 0.0f;

#pragma unroll 4
    for (int k = 0; k < 64; k++) {
        float ar[8], br[8];
        *reinterpret_cast<float4*>(&ar[0]) = *reinterpret_cast<const float4*>(&Zs[k * 132 + ty * 8]);
        *reinterpret_cast<float4*>(&ar[4]) = *reinterpret_cast<const float4*>(&Zs[k * 132 + ty * 8 + 4]);
        *reinterpret_cast<float4*>(&br[0]) = *reinterpret_cast<const float4*>(&Ws[k * 132 + tx * 8]);
        *reinterpret_cast<float4*>(&br[4]) = *reinterpret_cast<const float4*>(&Ws[k * 132 + tx * 8 + 4]);
#pragma unroll
        for (int i = 0; i < 8; i++)
#pragma unroll
            for (int j = 0; j < 8; j++)
                acc[i][j] = fmaf(ar[i], br[j], acc[i][j]);
    }
#pragma unroll
    for (int i = 0; i < 8; i++)
#pragma unroll
        for (int j = 0; j < 8; j++)
            acc[i][j] = sigm(acc[i][j] + sfb[tx * 8 + j]);

    __syncthreads();
    float* Os = ds;    // [128 b][64 m]

#pragma unroll
    for (int jj = 0; jj < 4; jj++) {
        int m = (n0 >> 1) + tx * 4 + jj;
        float4 w0 = *reinterpret_cast<const float4*>(&hw[(size_t)m * 4]);
        float4 w1 = *reinterpret_cast<const float4*>(&hw[((size_t)M_DIM + m) * 4]);
        float b00 = hb[2 * m],          b01 = hb[2 * m + 1];
        float b10 = hb[H_DIM + 2 * m],  b11 = hb[H_DIM + 2 * m + 1];
        float2 owv = *reinterpret_cast<const float2*>(&ow[2 * m]);
        float obv = ob[m];
#pragma unroll
        for (int i = 0; i < 8; i++) {
            float a0 = acc[i][2 * jj], a1 = acc[i][2 * jj + 1];
            float t0 = sigm(fmaf(a0, w0.x, fmaf(a1, w0.y, b00)));
            float t1 = sigm(fmaf(a0, w0.z, fmaf(a1, w0.w, b01)));
            a0 = sigm(fmaf(t0, w1.x, fmaf(t1, w1.y, b10)));
            a1 = sigm(fmaf(t0, w1.z, fmaf(t1, w1.w, b11)));
            Os[(ty * 8 + i) * 64 + tx * 4 + jj] = fmaf(a0, owv.x, fmaf(a1, owv.y, obv));
        }
    }
    __syncthreads();

#pragma unroll
    for (int it = 0; it < 8; it++) {
        int idx = tid + it * 256;
        int row = idx >> 4, mq = (idx & 15) * 4;
        float4 v = *reinterpret_cast<const float4*>(&Os[row * 64 + mq]);
        *reinterpret_cast<float4*>(&out[out_off + (size_t)(b0 + row) * M_DIM + (n0 >> 1) + mq]) = v;
    }
}

// ===================== launch =====================
extern "C" void kernel_launch(void* const* d_in, const int* in_sizes, int n_in,
                              void* d_out, int out_size)
{
    const float* x        = (const float*)d_in[0];
    const float* eps      = (const float*)d_in[1];
    const float* enc1_w   = (const float*)d_in[2];
    const float* enc1_b   = (const float*)d_in[3];
    const float* enc2_w   = (const float*)d_in[4];
    const float* enc2_b   = (const float*)d_in[5];
    const float* mu_w     = (const float*)d_in[6];
    const float* mu_b     = (const float*)d_in[7];
    const float* lv_w     = (const float*)d_in[8];
    const float* lv_b     = (const float*)d_in[9];
    const float* m_ful_w  = (const float*)d_in[10];
    const float* m_ful_b  = (const float*)d_in[11];
    const float* m_h_w    = (const float*)d_in[12];
    const float* m_h_b    = (const float*)d_in[13];
    const float* m_out_w  = (const float*)d_in[14];
    const float* m_out_b  = (const float*)d_in[15];
    const float* c_ful_w  = (const float*)d_in[16];
    const float* c_ful_b  = (const float*)d_in[17];
    const float* c_h_w    = (const float*)d_in[18];
    const float* c_h_b    = (const float*)d_in[19];
    const float* c_out_w  = (const float*)d_in[20];
    const float* c_out_b  = (const float*)d_in[21];
    float* out = (float*)d_out;

    __half *xh, *w1h, *w2h, *wch, *h1h, *h2h;
    float *mulv, *z;
    cudaGetSymbolAddress((void**)&xh,   g_xh);
    cudaGetSymbolAddress((void**)&w1h,  g_w1h);
    cudaGetSymbolAddress((void**)&w2h,  g_w2h);
    cudaGetSymbolAddress((void**)&wch,  g_wch);
    cudaGetSymbolAddress((void**)&h1h,  g_h1h);
    cudaGetSymbolAddress((void**)&h2h,  g_h2h);
    cudaGetSymbolAddress((void**)&mulv, g_mulv);
    cudaGetSymbolAddress((void**)&z,    g_z);

    cudaFuncSetAttribute((const void*)gemm_h16_kernel<__half, ACT_RELU, false>,
                         cudaFuncAttributeMaxDynamicSharedMemorySize, SM_GEMM_TOTAL);
    cudaFuncSetAttribute((const void*)gemm_h16_kernel<float, ACT_NONE, true>,
                         cudaFuncAttributeMaxDynamicSharedMemorySize, SM_GEMM_TOTAL);
    cudaFuncSetAttribute((const void*)decoder_kernel,
                         cudaFuncAttributeMaxDynamicSharedMemorySize, DEC_SMEM);

    // ---- main stream: x + enc1_w conversion FIRST (alone, full bandwidth) ----
    f2hA_kernel<<<(NX8 + NW8 + 255) / 256, 256>>>(x, enc1_w, xh, w1h);

    // ---- fork AFTER f2hA: f2hB + memset run concurrently with GEMM1,
    //      which is tensor-rate-bound (DRAM 4%) and leaves CTA slots free ----
    cudaEventRecord(g_side.fork, 0);
    cudaStreamWaitEvent(g_side.s, g_side.fork, 0);
    f2hB_kernel<<<(NW8 + 2 * NC8 + 255) / 256, 256, 0, g_side.s>>>(
        enc2_w, mu_w, lv_w, w2h, wch);
    cudaMemsetAsync(mulv, 0, B_DIM * 128 * sizeof(float), g_side.s);
    cudaEventRecord(g_side.join, g_side.s);

    // ---- GEMM1 on main stream (overlapped with f2hB) ----
    dim3 g1(M_DIM / 128, B_DIM / 128);
    gemm_h16_kernel<__half, ACT_RELU, false><<<g1, 512, SM_GEMM_TOTAL>>>(
        xh,  w1h, enc1_b, h1h, M_DIM, M_DIM, M_DIM);

    // ---- join: need w2h (+ wch, mulv zeroed) before GEMM2 / mulv ----
    cudaStreamWaitEvent(0, g_side.join, 0);

    gemm_h16_kernel<__half, ACT_RELU, false><<<g1, 512, SM_GEMM_TOTAL>>>(
        h1h, w2h, enc2_b, h2h, M_DIM, M_DIM, M_DIM);

    // ---- mu / logvar projection: split-K tensor GEMM (atomic accumulate) ----
    dim3 g2(1, B_DIM / 128, 8);   // N=128 tile, 8 M-tiles, 8 K-chunks of 512
    gemm_h16_kernel<float, ACT_NONE, true><<<g2, 512, SM_GEMM_TOTAL>>>(
        h2h, wch, nullptr, mulv, 128, M_DIM, 512);

    z_kernel<<<(B_DIM * Z_DIM + 255) / 256, 256>>>(mulv, eps, mu_b, lv_b, z, out);

    // ---- fused decoder (both branches) ----
    dim3 g3(H_DIM / 128, B_DIM / 128, 2);
    decoder_kernel<<<g3, 256, DEC_SMEM>>>(
        z,
        m_ful_w, m_ful_b, m_h_w, m_h_b, m_out_w, m_out_b,
        c_ful_w, c_ful_b, c_h_w, c_h_b, c_out_w, c_out_b,
        out);
}

// round 11
// speedup vs baseline: 1.0133x; 1.0079x over previous
#include <cuda_runtime.h>
#include <cuda_fp16.h>
#include <cstdint>
#include <cstddef>

// Problem dims (fixed)
#define B_DIM 1024
#define M_DIM 4096
#define W_DIM 2
#define L_DIM 2
#define Z_DIM 64
#define H_DIM 8192   // M*W

// Output layout: x_recon [B*M], logcov [B*M], mu [B*Z], logvar [B*Z]
#define OFF_XREC  0
#define OFF_LCOV  (B_DIM * M_DIM)
#define OFF_MU    (2 * B_DIM * M_DIM)
#define OFF_LV    (2 * B_DIM * M_DIM + B_DIM * Z_DIM)

#define KSPLIT 8   // mulv split-K chunks (Kchunk = 512)

// -------- scratch (no allocations allowed; __device__ globals) --------
__device__ __half g_xh  [B_DIM * M_DIM];   // x in fp16
__device__ __half g_w1h [M_DIM * M_DIM];   // enc1_w in fp16
__device__ __half g_w2h [M_DIM * M_DIM];   // enc2_w in fp16
__device__ __half g_wch [128 * M_DIM];     // concat(mu_w, lv_w) in fp16
__device__ __half g_h1h [B_DIM * M_DIM];   // encoder layer-1 out (fp16)
__device__ __half g_h2h [B_DIM * M_DIM];   // encoder layer-2 out (fp16)
__device__ float  g_mulvp[KSPLIT * B_DIM * 128];  // split-K partial sums
__device__ float  g_z[B_DIM * Z_DIM];

__device__ __forceinline__ float sigm(float x) { return 1.0f / (1.0f + expf(-x)); }

#define ACT_NONE 0
#define ACT_RELU 1

// ===================== merged fp32 -> fp16 conversion =====================
#define NX8 (B_DIM * M_DIM / 8)
#define NW8 (M_DIM * M_DIM / 8)
#define NC8 (64 * M_DIM / 8)
#define NTOT8 (NX8 + 2 * NW8 + 2 * NC8)

__device__ __forceinline__ void cvt8(const float* __restrict__ in, __half* __restrict__ out, int j) {
    const float4* p = reinterpret_cast<const float4*>(in) + 2 * (size_t)j;
    float4 a = p[0], b = p[1];
    __half2 h0 = __floats2half2_rn(a.x, a.y);
    __half2 h1 = __floats2half2_rn(a.z, a.w);
    __half2 h2 = __floats2half2_rn(b.x, b.y);
    __half2 h3 = __floats2half2_rn(b.z, b.w);
    uint4 u;
    u.x = *reinterpret_cast<uint32_t*>(&h0);
    u.y = *reinterpret_cast<uint32_t*>(&h1);
    u.z = *reinterpret_cast<uint32_t*>(&h2);
    u.w = *reinterpret_cast<uint32_t*>(&h3);
    reinterpret_cast<uint4*>(out)[j] = u;
}

__global__ void __launch_bounds__(256) f2h5_kernel(
    const float* __restrict__ x,  const float* __restrict__ w1,
    const float* __restrict__ w2, const float* __restrict__ muw,
    const float* __restrict__ lvw,
    __half* __restrict__ xh, __half* __restrict__ w1h,
    __half* __restrict__ w2h, __half* __restrict__ wch)
{
    int i = blockIdx.x * 256 + threadIdx.x;
    if (i < NX8)                      cvt8(x,   xh,  i);
    else if (i < NX8 + NW8)           cvt8(w1,  w1h, i - NX8);
    else if (i < NX8 + 2 * NW8)       cvt8(w2,  w2h, i - NX8 - NW8);
    else if (i < NX8 + 2 * NW8 + NC8) cvt8(muw, wch, i - NX8 - 2 * NW8);
    else if (i < NTOT8)               cvt8(lvw, wch + 64 * M_DIM, i - NX8 - 2 * NW8 - NC8);
}

// ===================== fp16 cp.async tensor-core GEMM =====================
__device__ __forceinline__ uint32_t smem_u32(const void* p) {
    uint32_t a;
    asm("{ .reg .u64 t; cvta.to.shared.u64 t, %1; cvt.u32.u64 %0, t; }" : "=r"(a) : "l"(p));
    return a;
}
__device__ __forceinline__ void ldmx4(uint32_t* r, uint32_t addr) {
    asm volatile("ldmatrix.sync.aligned.m8n8.x4.shared.b16 {%0,%1,%2,%3}, [%4];"
                 : "=r"(r[0]), "=r"(r[1]), "=r"(r[2]), "=r"(r[3]) : "r"(addr));
}
__device__ __forceinline__ void mma_f16(float* d, const uint32_t* a, const uint32_t* b) {
    asm volatile(
        "mma.sync.aligned.m16n8k16.row.col.f32.f16.f16.f32 "
        "{%0,%1,%2,%3}, {%4,%5,%6,%7}, {%8,%9}, {%0,%1,%2,%3};\n"
        : "+f"(d[0]), "+f"(d[1]), "+f"(d[2]), "+f"(d[3])
        : "r"(a[0]), "r"(a[1]), "r"(a[2]), "r"(a[3]), "r"(b[0]), "r"(b[1]));
}
__device__ __forceinline__ void cp_async16(uint32_t smem_addr, const void* gptr) {
    asm volatile("cp.async.cg.shared.global [%0], [%1], 16;\n" :: "r"(smem_addr), "l"(gptr));
}
__device__ __forceinline__ void cp_commit() { asm volatile("cp.async.commit_group;\n"); }
template <int N> __device__ __forceinline__ void cp_wait() {
    asm volatile("cp.async.wait_group %0;\n" :: "n"(N));
}

#define HS_ROW   80
#define HS_TILE  (128 * HS_ROW)
#define HS_STAGE (2 * HS_TILE)
#define N_STAGES 4
#define SM_GEMM_TOTAL (N_STAGES * HS_STAGE)   // 81920 B dynamic

// SPLITK: C points at partial buffer; CTA (z) writes its own [128x128] slice
// at C + z*B_DIM*128 with plain stores (no memset, no atomics).
template <typename OT, int ACT, bool SPLITK>
__global__ void __launch_bounds__(512, 2) gemm_h16_kernel(
    const __half* __restrict__ A, const __half* __restrict__ Wt,
    const float* __restrict__ bias, OT* __restrict__ C,
    int Ndim, int Kstride, int Kchunk)
{
    extern __shared__ __align__(16) uint8_t dsm[];
    __shared__ float sbias[128];

    const int tid  = threadIdx.x;
    const int lane = tid & 31;
    const int warp = tid >> 5;
    const int wm   = (warp & 3) * 32;
    const int wn   = (warp >> 2) * 32;
    const int m0   = blockIdx.y * 128;
    const int n0   = blockIdx.x * 128;
    const int koff = SPLITK ? blockIdx.z * Kchunk : 0;
    const uint32_t sb = smem_u32(dsm);

    if (!SPLITK && tid < 128) sbias[tid] = bias[n0 + tid];

    const int rC = tid >> 2;
    const int kC = (tid & 3) * 8;
    const uint32_t dC = (uint32_t)rC * HS_ROW + kC * 2;

    const __half* Ab = A  + (size_t)m0 * Kstride + koff;
    const __half* Bb = Wt + (size_t)n0 * Kstride + koff;

    const int T = Kchunk >> 5;

    auto issue = [&](int it) {
        uint32_t st = sb + (it & (N_STAGES - 1)) * HS_STAGE;
        cp_async16(st + dC,           Ab + (size_t)rC * Kstride + it * 32 + kC);
        cp_async16(st + HS_TILE + dC, Bb + (size_t)rC * Kstride + it * 32 + kC);
        cp_commit();
    };

    const uint32_t a_lm = ((lane & 7) + ((lane >> 3) & 1) * 8) * HS_ROW + ((lane >> 4) & 1) * 16;
    const uint32_t b_lm = ((lane & 7) + ((lane >> 4) & 1) * 8) * HS_ROW + ((lane >> 3) & 1) * 16;

    float acc[2][4][4];
#pragma unroll
    for (int i = 0; i < 2; i++)
#pragma unroll
        for (int j = 0; j < 4; j++)
#pragma unroll
            for (int r = 0; r < 4; r++) acc[i][j][r] = 0.0f;

#pragma unroll
    for (int i = 0; i < N_STAGES - 1; i++) issue(i);

    for (int it = 0; it < T; ++it) {
        cp_wait<N_STAGES - 2>();
        __syncthreads();

        if (it + N_STAGES - 1 < T) issue(it + N_STAGES - 1);
        else cp_commit();

        const uint32_t sa  = sb + (it & (N_STAGES - 1)) * HS_STAGE;
        const uint32_t sbm = sa + HS_TILE;
#pragma unroll
        for (int kk = 0; kk < 2; kk++) {
            uint32_t af[2][4], bf[2][4];
#pragma unroll
            for (int im = 0; im < 2; im++)
                ldmx4(af[im], sa + (wm + im * 16) * HS_ROW + a_lm + kk * 32);
#pragma unroll
            for (int jn = 0; jn < 2; jn++)
                ldmx4(bf[jn], sbm + (wn + jn * 16) * HS_ROW + b_lm + kk * 32);
#pragma unroll
            for (int im = 0; im < 2; im++)
#pragma unroll
                for (int jn = 0; jn < 2; jn++) {
                    mma_f16(acc[im][2 * jn],     af[im], &bf[jn][0]);
                    mma_f16(acc[im][2 * jn + 1], af[im], &bf[jn][2]);
                }
        }
    }

    const int g = lane >> 2, t = lane & 3;
#pragma unroll
    for (int im = 0; im < 2; im++) {
        int r0 = m0 + wm + im * 16 + g;
#pragma unroll
        for (int in_ = 0; in_ < 4; in_++) {
            int cl = wn + in_ * 8 + t * 2;
            int c = n0 + cl;
            if (SPLITK) {
                float* Cf = reinterpret_cast<float*>(C) + (size_t)blockIdx.z * B_DIM * 128;
                *reinterpret_cast<float2*>(&Cf[(size_t)r0 * Ndim + c]) =
                    make_float2(acc[im][in_][0], acc[im][in_][1]);
                *reinterpret_cast<float2*>(&Cf[(size_t)(r0 + 8) * Ndim + c]) =
                    make_float2(acc[im][in_][2], acc[im][in_][3]);
            } else {
                float b0v = sbias[cl], b1v = sbias[cl + 1];
                float v00 = acc[im][in_][0] + b0v;
                float v01 = acc[im][in_][1] + b1v;
                float v10 = acc[im][in_][2] + b0v;
                float v11 = acc[im][in_][3] + b1v;
                if (ACT == ACT_RELU) {
                    v00 = fmaxf(v00, 0.0f); v01 = fmaxf(v01, 0.0f);
                    v10 = fmaxf(v10, 0.0f); v11 = fmaxf(v11, 0.0f);
                }
                if (sizeof(OT) == 2) {
                    __half* Ch = reinterpret_cast<__half*>(C);
                    __half2 lo = __floats2half2_rn(v00, v01);
                    __half2 hi = __floats2half2_rn(v10, v11);
                    *reinterpret_cast<__half2*>(&Ch[(size_t)r0 * Ndim + c]) = lo;
                    *reinterpret_cast<__half2*>(&Ch[(size_t)(r0 + 8) * Ndim + c]) = hi;
                } else {
                    float* Cf = reinterpret_cast<float*>(C);
                    *reinterpret_cast<float2*>(&Cf[(size_t)r0 * Ndim + c]) = make_float2(v00, v01);
                    *reinterpret_cast<float2*>(&Cf[(size_t)(r0 + 8) * Ndim + c]) = make_float2(v10, v11);
                }
            }
        }
    }
}

// ===================== reparameterization + mu/logvar output (sums partials) =========
__global__ void z_kernel(const float* __restrict__ mulvp, const float* __restrict__ eps,
                         const float* __restrict__ mu_b, const float* __restrict__ lv_b,
                         float* __restrict__ z, float* __restrict__ out)
{
    int idx = blockIdx.x * 256 + threadIdx.x;
    if (idx >= B_DIM * Z_DIM) return;
    int b = idx >> 6, j = idx & 63;
    float mu = mu_b[j], lv = lv_b[j];
#pragma unroll
    for (int s = 0; s < KSPLIT; s++) {
        const float* p = mulvp + (size_t)s * B_DIM * 128 + (size_t)b * 128;
        mu += p[j];
        lv += p[64 + j];
    }
    z[idx] = mu + expf(0.5f * lv) * eps[idx];
    out[OFF_MU + idx] = mu;
    out[OFF_LV + idx] = lv;
}

// ===================== fused decoder: fulcon GEMM + block-diag layers + output =======
#define DEC_SMEM (2 * 64 * 132 * 4)    // 67584 B

__global__ void __launch_bounds__(256) decoder_kernel(
    const float* __restrict__ z,
    const float* __restrict__ m_ful_w, const float* __restrict__ m_ful_b,
    const float* __restrict__ m_h_w,   const float* __restrict__ m_h_b,
    const float* __restrict__ m_out_w, const float* __restrict__ m_out_b,
    const float* __restrict__ c_ful_w, const float* __restrict__ c_ful_b,
    const float* __restrict__ c_h_w,   const float* __restrict__ c_h_b,
    const float* __restrict__ c_out_w, const float* __restrict__ c_out_b,
    float* __restrict__ out)
{
    extern __shared__ float ds[];
    float* Zs = ds;               // [64 k][132]
    float* Ws = ds + 64 * 132;    // [64 k][132]
    __shared__ float sfb[128];

    const bool mean = (blockIdx.z == 0);
    const float* fw = mean ? m_ful_w : c_ful_w;
    const float* fb = mean ? m_ful_b : c_ful_b;
    const float* hw = mean ? m_h_w   : c_h_w;
    const float* hb = mean ? m_h_b   : c_h_b;
    const float* ow = mean ? m_out_w : c_out_w;
    const float* ob = mean ? m_out_b : c_out_b;
    const int out_off = mean ? OFF_XREC : OFF_LCOV;

    const int tid = threadIdx.x;
    const int tx  = tid & 15;
    const int ty  = tid >> 4;
    const int n0  = blockIdx.x * 128;
    const int b0  = blockIdx.y * 128;

#pragma unroll
    for (int it = 0; it < 8; it++) {
        int idx = tid + it * 256;
        int row = idx >> 4, kq = (idx & 15) * 4;
        float4 v = *reinterpret_cast<const float4*>(&z[(size_t)(b0 + row) * 64 + kq]);
        Zs[(kq + 0) * 132 + row] = v.x; Zs[(kq + 1) * 132 + row] = v.y;
        Zs[(kq + 2) * 132 + row] = v.z; Zs[(kq + 3) * 132 + row] = v.w;
    }
#pragma unroll
    for (int it = 0; it < 8; it++) {
        int idx = tid + it * 256;
        int row = idx >> 4, kq = (idx & 15) * 4;
        float4 v = *reinterpret_cast<const float4*>(&fw[(size_t)(n0 + row) * 64 + kq]);
        Ws[(kq + 0) * 132 + row] = v.x; Ws[(kq + 1) * 132 + row] = v.y;
        Ws[(kq + 2) * 132 + row] = v.z; Ws[(kq + 3) * 132 + row] = v.w;
    }
    if (tid < 128) sfb[tid] = fb[n0 + tid];
    __syncthreads();

    float acc[8][8];
#pragma unroll
    for (int i = 0; i < 8; i++)
#pragma unroll
        for (int j = 0; j < 8; j++) acc[i][j] = 0.0f;

#pragma unroll 4
    for (int k = 0; k < 64; k++) {
        float ar[8], br[8];
        *reinterpret_cast<float4*>(&ar[0]) = *reinterpret_cast<const float4*>(&Zs[k * 132 + ty * 8]);
        *reinterpret_cast<float4*>(&ar[4]) = *reinterpret_cast<const float4*>(&Zs[k * 132 + ty * 8 + 4]);
        *reinterpret_cast<float4*>(&br[0]) = *reinterpret_cast<const float4*>(&Ws[k * 132 + tx * 8]);
        *reinterpret_cast<float4*>(&br[4]) = *reinterpret_cast<const float4*>(&Ws[k * 132 + tx * 8 + 4]);
#pragma unroll
        for (int i = 0; i < 8; i++)
#pragma unroll
            for (int j = 0; j < 8; j++)
                acc[i][j] = fmaf(ar[i], br[j], acc[i][j]);
    }
#pragma unroll
    for (int i = 0; i < 8; i++)
#pragma unroll
        for (int j = 0; j < 8; j++)
            acc[i][j] = sigm(acc[i][j] + sfb[tx * 8 + j]);

    __syncthreads();
    float* Os = ds;    // [128 b][64 m]

#pragma unroll
    for (int jj = 0; jj < 4; jj++) {
        int m = (n0 >> 1) + tx * 4 + jj;
        float4 w0 = *reinterpret_cast<const float4*>(&hw[(size_t)m * 4]);
        float4 w1 = *reinterpret_cast<const float4*>(&hw[((size_t)M_DIM + m) * 4]);
        float b00 = hb[2 * m],          b01 = hb[2 * m + 1];
        float b10 = hb[H_DIM + 2 * m],  b11 = hb[H_DIM + 2 * m + 1];
        float2 owv = *reinterpret_cast<const float2*>(&ow[2 * m]);
        float obv = ob[m];
#pragma unroll
        for (int i = 0; i < 8; i++) {
            float a0 = acc[i][2 * jj], a1 = acc[i][2 * jj + 1];
            float t0 = sigm(fmaf(a0, w0.x, fmaf(a1, w0.y, b00)));
            float t1 = sigm(fmaf(a0, w0.z, fmaf(a1, w0.w, b01)));
            a0 = sigm(fmaf(t0, w1.x, fmaf(t1, w1.y, b10)));
            a1 = sigm(fmaf(t0, w1.z, fmaf(t1, w1.w, b11)));
            Os[(ty * 8 + i) * 64 + tx * 4 + jj] = fmaf(a0, owv.x, fmaf(a1, owv.y, obv));
        }
    }
    __syncthreads();

#pragma unroll
    for (int it = 0; it < 8; it++) {
        int idx = tid + it * 256;
        int row = idx >> 4, mq = (idx & 15) * 4;
        float4 v = *reinterpret_cast<const float4*>(&Os[row * 64 + mq]);
        *reinterpret_cast<float4*>(&out[out_off + (size_t)(b0 + row) * M_DIM + (n0 >> 1) + mq]) = v;
    }
}

// ===================== launch =====================
extern "C" void kernel_launch(void* const* d_in, const int* in_sizes, int n_in,
                              void* d_out, int out_size)
{
    const float* x        = (const float*)d_in[0];
    const float* eps      = (const float*)d_in[1];
    const float* enc1_w   = (const float*)d_in[2];
    const float* enc1_b   = (const float*)d_in[3];
    const float* enc2_w   = (const float*)d_in[4];
    const float* enc2_b   = (const float*)d_in[5];
    const float* mu_w     = (const float*)d_in[6];
    const float* mu_b     = (const float*)d_in[7];
    const float* lv_w     = (const float*)d_in[8];
    const float* lv_b     = (const float*)d_in[9];
    const float* m_ful_w  = (const float*)d_in[10];
    const float* m_ful_b  = (const float*)d_in[11];
    const float* m_h_w    = (const float*)d_in[12];
    const float* m_h_b    = (const float*)d_in[13];
    const float* m_out_w  = (const float*)d_in[14];
    const float* m_out_b  = (const float*)d_in[15];
    const float* c_ful_w  = (const float*)d_in[16];
    const float* c_ful_b  = (const float*)d_in[17];
    const float* c_h_w    = (const float*)d_in[18];
    const float* c_h_b    = (const float*)d_in[19];
    const float* c_out_w  = (const float*)d_in[20];
    const float* c_out_b  = (const float*)d_in[21];
    float* out = (float*)d_out;

    __half *xh, *w1h, *w2h, *wch, *h1h, *h2h;
    float *mulvp, *z;
    cudaGetSymbolAddress((void**)&xh,    g_xh);
    cudaGetSymbolAddress((void**)&w1h,   g_w1h);
    cudaGetSymbolAddress((void**)&w2h,   g_w2h);
    cudaGetSymbolAddress((void**)&wch,   g_wch);
    cudaGetSymbolAddress((void**)&h1h,   g_h1h);
    cudaGetSymbolAddress((void**)&h2h,   g_h2h);
    cudaGetSymbolAddress((void**)&mulvp, g_mulvp);
    cudaGetSymbolAddress((void**)&z,     g_z);

    cudaFuncSetAttribute((const void*)gemm_h16_kernel<__half, ACT_RELU, false>,
                         cudaFuncAttributeMaxDynamicSharedMemorySize, SM_GEMM_TOTAL);
    cudaFuncSetAttribute((const void*)gemm_h16_kernel<float, ACT_NONE, true>,
                         cudaFuncAttributeMaxDynamicSharedMemorySize, SM_GEMM_TOTAL);
    cudaFuncSetAttribute((const void*)decoder_kernel,
                         cudaFuncAttributeMaxDynamicSharedMemorySize, DEC_SMEM);

    // ---- prep: fp32 -> fp16 (x, enc1_w, enc2_w, mu_w|lv_w) in one launch ----
    f2h5_kernel<<<(NTOT8 + 255) / 256, 256>>>(x, enc1_w, enc2_w, mu_w, lv_w,
                                              xh, w1h, w2h, wch);

    // ---- encoder GEMMs (mma.sync fp16 path, at its rate ceiling) ----
    dim3 g1(M_DIM / 128, B_DIM / 128);
    gemm_h16_kernel<__half, ACT_RELU, false><<<g1, 512, SM_GEMM_TOTAL>>>(
        xh,  w1h, enc1_b, h1h, M_DIM, M_DIM, M_DIM);
    gemm_h16_kernel<__half, ACT_RELU, false><<<g1, 512, SM_GEMM_TOTAL>>>(
        h1h, w2h, enc2_b, h2h, M_DIM, M_DIM, M_DIM);

    // ---- mu / logvar projection: split-K into partial buffers (no memset/atomics) ----
    dim3 g2(1, B_DIM / 128, KSPLIT);   // N=128 tile, 8 M-tiles, 8 K-chunks of 512
    gemm_h16_kernel<float, ACT_NONE, true><<<g2, 512, SM_GEMM_TOTAL>>>(
        h2h, wch, nullptr, mulvp, 128, M_DIM, M_DIM / KSPLIT);

    // ---- z: sum partials + bias + reparameterize ----
    z_kernel<<<(B_DIM * Z_DIM + 255) / 256, 256>>>(mulvp, eps, mu_b, lv_b, z, out);

    // ---- fused decoder (both branches) ----
    dim3 g3(H_DIM / 128, B_DIM / 128, 2);
    decoder_kernel<<<g3, 256, DEC_SMEM>>>(
        z,
        m_ful_w, m_ful_b, m_h_w, m_h_b, m_out_w, m_out_b,
        c_ful_w, c_ful_b, c_h_w, c_h_b, c_out_w, c_out_b,
        out);
}